// round 16
// baseline (speedup 1.0000x reference)
#include <cuda_runtime.h>
#include <cuda_bf16.h>
#include <math.h>
#include <stdint.h>

// Problem dims (fixed by the reference)
#define T_DIM 8192
#define E_DIM 1024
#define V_DIM 50000

#define CAP     4096          // pre-candidate slots per row
#define WIN     22.0f         // pruning window (>= 20.72 + 1.0 + bf16 slack)
#define NWLOG   20.72f        // -ln(1e-9)
#define MARGIN  1.0f

// Scratch (allocation-free rule: __device__ globals)
__device__ float g_X[(size_t)T_DIM * E_DIM];                  // only if W != I
__device__ float g_Ld[T_DIM];
__device__ __nv_bfloat16 g_Xh[(size_t)T_DIM * E_DIM];         // 16 MB
__device__ __nv_bfloat16 g_Vh[(size_t)V_DIM * E_DIM];         // 100 MB
__device__ int2     g_cand[(size_t)T_DIM * CAP];              // 268 MB
__device__ int      g_cnt[T_DIM];
__device__ unsigned g_Mg[T_DIM];
__device__ int      g_Wident;                                 // W == identity?

// ===========================================================================
// helpers
// ===========================================================================
__device__ __forceinline__ uint32_t smem_u32(const void* p) {
    uint32_t a;
    asm("{ .reg .u64 t; cvta.to.shared.u64 t, %1; cvt.u32.u64 %0, t; }"
        : "=r"(a) : "l"(p));
    return a;
}

__device__ __forceinline__ void cp16(uint32_t dst, const void* src, uint32_t sz) {
    asm volatile("cp.async.cg.shared.global [%0], [%1], 16, %2;"
                 :: "r"(dst), "l"(src), "r"(sz) : "memory");
}

__device__ __forceinline__ void ldsm_x4(uint32_t& r0, uint32_t& r1,
                                        uint32_t& r2, uint32_t& r3, uint32_t addr) {
    asm volatile("ldmatrix.sync.aligned.m8n8.x4.shared.b16 {%0,%1,%2,%3}, [%4];"
                 : "=r"(r0), "=r"(r1), "=r"(r2), "=r"(r3) : "r"(addr));
}

__device__ __forceinline__ void mma_bf16(float* c, const uint32_t* a,
                                         uint32_t b0, uint32_t b1) {
    asm volatile(
        "mma.sync.aligned.m16n8k16.row.col.f32.bf16.bf16.f32 "
        "{%0,%1,%2,%3}, {%4,%5,%6,%7}, {%8,%9}, {%0,%1,%2,%3};"
        : "+f"(c[0]), "+f"(c[1]), "+f"(c[2]), "+f"(c[3])
        : "r"(a[0]), "r"(a[1]), "r"(a[2]), "r"(a[3]), "r"(b0), "r"(b1));
}

__device__ __forceinline__ uint32_t swz(uint32_t o) { return o ^ ((o >> 3) & 0x70); }

// order-preserving float <-> uint for atomicMax
__device__ __forceinline__ unsigned fenc(float f) {
    unsigned u = __float_as_uint(f);
    return (u & 0x80000000u) ? ~u : (u | 0x80000000u);
}
__device__ __forceinline__ float fdec(unsigned u) {
    unsigned i = (u & 0x80000000u) ? (u & 0x7FFFFFFFu) : ~u;
    return __uint_as_float(i);
}

// ===========================================================================
// init: reset counters / maxima / identity flag (every launch -> replay safe)
// ===========================================================================
__global__ void __launch_bounds__(256) init_kernel() {
    int i = blockIdx.x * 256 + threadIdx.x;
    if (i < T_DIM) { g_cnt[i] = 0; g_Mg[i] = fenc(-3.0e38f); }
    if (i == 0) g_Wident = 1;
}

// ===========================================================================
// check whether W is exactly the identity matrix (device-side, graph-safe)
// ===========================================================================
__global__ void __launch_bounds__(256) check_ident_kernel(
    const float* __restrict__ W)
{
    int i = blockIdx.x * 256 + threadIdx.x;     // float4 index
    float4 v = ((const float4*)W)[i];
    int base = 4 * i;
    int row  = base >> 10;                       // /E_DIM
    int col  = base & (E_DIM - 1);
    float e0 = (row == col + 0) ? 1.f : 0.f;
    float e1 = (row == col + 1) ? 1.f : 0.f;
    float e2 = (row == col + 2) ? 1.f : 0.f;
    float e3 = (row == col + 3) ? 1.f : 0.f;
    if (v.x != e0 || v.y != e1 || v.z != e2 || v.w != e3) g_Wident = 0;
}

// ===========================================================================
// fp32 -> bf16 (hi only); 4 float4 per thread for MLP=4
// ===========================================================================
__global__ void __launch_bounds__(256) split_hi_kernel(
    const float* __restrict__ src, __nv_bfloat16* __restrict__ dst, int n4)
{
    int i0 = (blockIdx.x * 256 + threadIdx.x) * 4;
    const float4* s4 = (const float4*)src;
    __nv_bfloat162* d = (__nv_bfloat162*)dst;
    float4 v[4];
#pragma unroll
    for (int k = 0; k < 4; ++k) {
        int i = i0 + k;
        if (i < n4) v[k] = s4[i];
    }
#pragma unroll
    for (int k = 0; k < 4; ++k) {
        int i = i0 + k;
        if (i < n4) {
            d[2 * i]     = __nv_bfloat162(__float2bfloat16(v[k].x),
                                          __float2bfloat16(v[k].y));
            d[2 * i + 1] = __nv_bfloat162(__float2bfloat16(v[k].z),
                                          __float2bfloat16(v[k].w));
        }
    }
}

// ===========================================================================
// X-prep: identity -> Xh = bf16(tokens) directly (no X materialized);
// else exact fp32 GEMM X = tokens @ W, epilogue emits X (fp32) AND Xh (bf16)
// ===========================================================================
#define BM 128
#define BN 128
#define BK 16
#define TM 8
#define TN 8
#define SPAD 4

__global__ void __launch_bounds__(256) xprep_kernel(
    const float* __restrict__ A, const float* __restrict__ B,
    float* __restrict__ X, __nv_bfloat16* __restrict__ Xh)
{
    const int tid = threadIdx.x;
    const int bm = blockIdx.y * BM;
    const int bn = blockIdx.x * BN;

    if (g_Wident) {   // Xh tile = bf16(tokens tile); X not needed
        const float4* A4 = (const float4*)A;
        __nv_bfloat162* H2 = (__nv_bfloat162*)Xh;
#pragma unroll
        for (int r = 0; r < 16; ++r) {        // 128 rows x 32 float4 / 256 thr
            int f = tid + r * 256;
            int row = f >> 5, c4 = f & 31;
            float4 v = A4[(size_t)(bm + row) * (E_DIM / 4) + (bn >> 2) + c4];
            size_t h = (size_t)(bm + row) * (E_DIM / 2) + (bn >> 1) + c4 * 2;
            H2[h]     = __nv_bfloat162(__float2bfloat16(v.x), __float2bfloat16(v.y));
            H2[h + 1] = __nv_bfloat162(__float2bfloat16(v.z), __float2bfloat16(v.w));
        }
        return;
    }

    __shared__ float As[BK][BM + SPAD];
    __shared__ float Bs[BK][BN + SPAD];
    const int tx = tid & 15;
    const int ty = tid >> 4;

    float acc[TM][TN];
#pragma unroll
    for (int i = 0; i < TM; i++)
#pragma unroll
        for (int j = 0; j < TN; j++) acc[i][j] = 0.f;

    for (int k0 = 0; k0 < E_DIM; k0 += BK) {
#pragma unroll
        for (int r = 0; r < 2; r++) {
            int f = tid + r * 256;
            int row = f >> 2;
            int kq = (f & 3) * 4;
            float4 v = *(const float4*)&A[(size_t)(bm + row) * E_DIM + k0 + kq];
            As[kq + 0][row] = v.x; As[kq + 1][row] = v.y;
            As[kq + 2][row] = v.z; As[kq + 3][row] = v.w;
        }
#pragma unroll
        for (int r = 0; r < 2; r++) {
            int f = tid + r * 256;
            int kr = f >> 5;
            int nq = (f & 31) * 4;
            float4 v = *(const float4*)&B[(size_t)(k0 + kr) * E_DIM + bn + nq];
            Bs[kr][nq + 0] = v.x; Bs[kr][nq + 1] = v.y;
            Bs[kr][nq + 2] = v.z; Bs[kr][nq + 3] = v.w;
        }
        __syncthreads();
#pragma unroll
        for (int kk = 0; kk < BK; kk++) {
            float a[TM], b[TN];
#pragma unroll
            for (int i = 0; i < TM; i++) a[i] = As[kk][ty * TM + i];
#pragma unroll
            for (int j = 0; j < TN; j++) b[j] = Bs[kk][tx * TN + j];
#pragma unroll
            for (int i = 0; i < TM; i++)
#pragma unroll
                for (int j = 0; j < TN; j++) acc[i][j] += a[i] * b[j];
        }
        __syncthreads();
    }
#pragma unroll
    for (int i = 0; i < TM; i++) {
        int gm = bm + ty * TM + i;
#pragma unroll
        for (int j = 0; j < TN; j++)
            X[(size_t)gm * E_DIM + bn + tx * TN + j] = acc[i][j];
#pragma unroll
        for (int j = 0; j < TN; j += 2) {
            size_t h = ((size_t)gm * E_DIM + bn + tx * TN + j) >> 1;
            ((__nv_bfloat162*)Xh)[h] =
                __nv_bfloat162(__float2bfloat16(acc[i][j]),
                               __float2bfloat16(acc[i][j + 1]));
        }
    }
}

// ===========================================================================
// bf16 mma.sync GEMM + fused candidate extraction.
// 128x128 CTA tile, 256 threads, 2 CTAs/SM, 3-stage cp.async pipeline.
// Prefetch-FIRST mainloop: next-next stage loads issue before the mma block
// so wait_group at the next barrier is (almost) never exposed.
// ===========================================================================
#define GBK 64
#define KITERS (E_DIM / GBK)              // 16
#define STAGE_B 32768                     // A 16K + B 16K per stage
#define GEMM_SMEM (3 * STAGE_B)           // 96 KB -> 2 CTAs/SM

__global__ void __launch_bounds__(256, 2) mma_gemm_cand_kernel(
    const __nv_bfloat16* __restrict__ A, const __nv_bfloat16* __restrict__ B)
{
    extern __shared__ __align__(1024) char sm[];
    const uint32_t sbase = smem_u32(sm);
    const int tid  = threadIdx.x;
    const int lane = tid & 31;
    const int wid  = tid >> 5;
    const int bm = blockIdx.x * 128;
    const int bn = blockIdx.y * 128;
    const int wm = (wid >> 2) * 64;
    const int wn = (wid & 3) * 32;

    float acc[4][4][4];
#pragma unroll
    for (int mt = 0; mt < 4; mt++)
#pragma unroll
        for (int nt = 0; nt < 4; nt++)
#pragma unroll
            for (int r = 0; r < 4; r++) acc[mt][nt][r] = 0.f;

    auto load_stage = [&](int s, int k0) {
        uint32_t sa = sbase + s * STAGE_B;
#pragma unroll
        for (int r = 0; r < 4; ++r) {               // A: 128 rows x 128B
            int f = tid + r * 256;
            int row = f >> 3, q = f & 7;
            uint32_t so = swz((uint32_t)(row * 128 + q * 16));
            cp16(sa + so,
                 (const char*)(A + (size_t)(bm + row) * E_DIM + k0) + q * 16, 16u);
        }
#pragma unroll
        for (int r = 0; r < 4; ++r) {               // B: 128 rows x 128B (guard V)
            int f = tid + r * 256;
            int row = f >> 3, q = f & 7;
            int vr = bn + row;
            uint32_t so = swz((uint32_t)(row * 128 + q * 16));
            const char* src = (const char*)(
                B + (size_t)(vr < V_DIM ? vr : V_DIM - 1) * E_DIM + k0) + q * 16;
            cp16(sa + 16384 + so, src, vr < V_DIM ? 16u : 0u);
        }
    };

    load_stage(0, 0);
    asm volatile("cp.async.commit_group;" ::: "memory");
    load_stage(1, GBK);
    asm volatile("cp.async.commit_group;" ::: "memory");

    for (int it = 0; it < KITERS; ++it) {
        // need group #it complete; allow 1 pending except the last iter
        if (it < KITERS - 1)
            asm volatile("cp.async.wait_group 1;" ::: "memory");
        else
            asm volatile("cp.async.wait_group 0;" ::: "memory");
        __syncthreads();

        // PREFETCH FIRST: buffer (it+2)%3 was last read in iter it-1, which
        // every thread has finished (barrier above). Issuing the cp.async
        // before the mma block overlaps the loads with this iter's compute.
        if (it + 2 < KITERS) {
            load_stage((it + 2) % 3, (it + 2) * GBK);
            asm volatile("cp.async.commit_group;" ::: "memory");
        }

        uint32_t sa = sbase + (it % 3) * STAGE_B;
        uint32_t sb = sa + 16384;
#pragma unroll
        for (int ks = 0; ks < 4; ++ks) {
            uint32_t a[4][4], b[2][4];
#pragma unroll
            for (int mt = 0; mt < 4; ++mt) {
                int row  = wm + mt * 16 + (lane & 15);
                int colb = ks * 32 + ((lane >> 4) << 4);
                ldsm_x4(a[mt][0], a[mt][1], a[mt][2], a[mt][3],
                        sa + swz((uint32_t)(row * 128 + colb)));
            }
#pragma unroll
            for (int np = 0; np < 2; ++np) {
                int nrow = wn + np * 16 + ((lane >> 4) << 3) + (lane & 7);
                int colb = ks * 32 + (((lane >> 3) & 1) << 4);
                ldsm_x4(b[np][0], b[np][1], b[np][2], b[np][3],
                        sb + swz((uint32_t)(nrow * 128 + colb)));
            }
#pragma unroll
            for (int mt = 0; mt < 4; ++mt)
#pragma unroll
                for (int nt = 0; nt < 4; ++nt)
                    mma_bf16(acc[mt][nt], a[mt],
                             b[nt >> 1][(nt & 1) * 2], b[nt >> 1][(nt & 1) * 2 + 1]);
        }
    }
    __syncthreads();   // stage smem reused below

    // -------- fused epilogue: tile max -> atomicMax -> pruned append --------
    float* sm_m  = (float*)sm;            // [4][128]
    float* sm_mp = (float*)sm + 512;      // [128] combined(tile, running-global)

#pragma unroll
    for (int mt = 0; mt < 4; ++mt) {
        float v0 = -3.0e38f, v1 = -3.0e38f;
#pragma unroll
        for (int nt = 0; nt < 4; ++nt) {
            v0 = fmaxf(v0, fmaxf(acc[mt][nt][0], acc[mt][nt][1]));
            v1 = fmaxf(v1, fmaxf(acc[mt][nt][2], acc[mt][nt][3]));
        }
#pragma unroll
        for (int o = 1; o <= 2; o <<= 1) {
            v0 = fmaxf(v0, __shfl_xor_sync(0xffffffffu, v0, o));
            v1 = fmaxf(v1, __shfl_xor_sync(0xffffffffu, v1, o));
        }
        if ((lane & 3) == 0) {
            int r = wm + mt * 16 + (lane >> 2);
            sm_m[(wid & 3) * 128 + r]     = v0;
            sm_m[(wid & 3) * 128 + r + 8] = v1;
        }
    }
    __syncthreads();

    if (tid < 128) {
        float mp = fmaxf(fmaxf(sm_m[tid], sm_m[128 + tid]),
                         fmaxf(sm_m[256 + tid], sm_m[384 + tid]));
        unsigned old = atomicMax(&g_Mg[bm + tid], fenc(mp));
        sm_mp[tid] = fmaxf(mp, fdec(old));
    }
    __syncthreads();

#pragma unroll
    for (int mt = 0; mt < 4; ++mt) {
#pragma unroll
        for (int k = 0; k < 4; ++k) {
            int rloc = wm + mt * 16 + (lane >> 2) + ((k >> 1) << 3);
            float thr = sm_mp[rloc] - WIN;
#pragma unroll
            for (int nt = 0; nt < 4; ++nt) {
                float v = acc[mt][nt][k];
                if (v > thr) {
                    int col = bn + wn + nt * 8 + ((lane & 3) << 1) + (k & 1);
                    if (col < V_DIM) {
                        int gr = bm + rloc;
                        int slot = atomicAdd(&g_cnt[gr], 1);
                        if (slot < CAP)
                            g_cand[(size_t)gr * CAP + slot] =
                                make_int2(col, __float_as_int(v));
                    }
                }
            }
        }
    }
}

// ===========================================================================
// Ld[t] = dot(Xsrc[t,:], default_embedding)   (exact fp32; Xsrc per flag)
// ===========================================================================
__global__ void __launch_bounds__(256) dot_default_kernel(
    const float* __restrict__ tokens, const float* __restrict__ X,
    const float* __restrict__ d, float* __restrict__ Ld)
{
    const float* src = g_Wident ? tokens : X;
    int w = threadIdx.x >> 5;
    int lane = threadIdx.x & 31;
    int t = blockIdx.x * 8 + w;
    const float4* xr = (const float4*)(src + (size_t)t * E_DIM);
    const float4* dr = (const float4*)d;
    float s = 0.f;
    for (int q = lane; q < E_DIM / 4; q += 32) {
        float4 a = xr[q], b = dr[q];
        s += a.x * b.x + a.y * b.y + a.z * b.z + a.w * b.w;
    }
#pragma unroll
    for (int o = 16; o; o >>= 1) s += __shfl_xor_sync(0xffffffffu, s, o);
    if (lane == 0) Ld[t] = s;
}

// ===========================================================================
// Final: filter -> CHUNKED exact dot + weighted gather (L1-hot window).
// Softmax uses fixed reference Mg (cancels exactly).
// ===========================================================================
#define CAND_MAX 256
#define FCHUNK   8

__global__ void __launch_bounds__(256) finalize_kernel(
    const float* __restrict__ Ld, const float* __restrict__ tokens,
    const float* __restrict__ vocab, const float* __restrict__ X,
    float* __restrict__ out)
{
    const int t = blockIdx.x;
    const int tid = threadIdx.x;
    const int lane = tid & 31;
    const int wid = tid >> 5;

    __shared__ int   s_idx[CAND_MAX];
    __shared__ float s_part[FCHUNK][8];
    __shared__ float s_w[FCHUNK];
    __shared__ int   s_cnt;
    __shared__ float s_zu;
    __shared__ __align__(16) float sX[E_DIM];

    const float* xsrc = g_Wident ? tokens : X;
    ((float4*)sX)[tid] = ((const float4*)(xsrc + (size_t)t * E_DIM))[tid];
    if (tid == 0) { s_cnt = 0; s_zu = 0.f; }
    __syncthreads();

    const float ld = Ld[t];
    const float Mg = fdec(g_Mg[t]);
    const float cutoff = Mg - NWLOG - MARGIN;

    // filter pre-candidates
    const int pcnt = min(g_cnt[t], CAP);
    const int2* cl = &g_cand[(size_t)t * CAP];
    for (int i = tid; i < pcnt; i += 256) {
        int2 e = cl[i];
        if (__int_as_float(e.y) > cutoff) {
            int p = atomicAdd(&s_cnt, 1);
            if (p < CAND_MAX) s_idx[p] = e.x;
        }
    }
    __syncthreads();
    const int cnt = min(s_cnt, CAND_MAX);

    const float4 x = ((const float4*)sX)[wid * 32 + lane];
    float4 acc = make_float4(0.f, 0.f, 0.f, 0.f);

    for (int c0 = 0; c0 < cnt; c0 += FCHUNK) {
        const int m = min(FCHUNK, cnt - c0);

        // exact fp32 dots for this chunk (warp-split, deterministic)
        for (int j = 0; j < m; ++j) {
            const float4* vr = (const float4*)(vocab + (size_t)s_idx[c0 + j] * E_DIM);
            float4 v = vr[wid * 32 + lane];
            float s = x.x * v.x + x.y * v.y + x.z * v.z + x.w * v.w;
#pragma unroll
            for (int o = 16; o; o >>= 1) s += __shfl_xor_sync(0xffffffffu, s, o);
            if (lane == 0) s_part[j][wid] = s;
        }
        __syncthreads();

        if (tid < m) {
            float d = 0.f;
#pragma unroll
            for (int w = 0; w < 8; ++w) d += s_part[tid][w];
            s_w[tid] = __expf(d - Mg);        // unnormalized weight
        }
        __syncthreads();

        if (tid == 0) {
            float z = 0.f;
            for (int j = 0; j < m; ++j) z += s_w[j];
            s_zu += z;
        }
        // weighted gather — rows are L1-hot from the dot pass just above
        for (int j = 0; j < m; ++j) {
            float w = s_w[j];
            float4 v = ((const float4*)(vocab + (size_t)s_idx[c0 + j] * E_DIM))[tid];
            acc.x += w * v.x; acc.y += w * v.y;
            acc.z += w * v.z; acc.w += w * v.w;
        }
        __syncthreads();   // protect s_part/s_w reuse and s_zu ordering
    }

    const float wdef_u = __expf(ld - Mg);
    const float inv = 1.0f / (s_zu + wdef_u);
    const float wdef = wdef_u * inv;

    float4 tk = ((const float4*)(tokens + (size_t)t * E_DIM))[tid];
    float4 o4 = make_float4(acc.x * inv + wdef * tk.x,
                            acc.y * inv + wdef * tk.y,
                            acc.z * inv + wdef * tk.z,
                            acc.w * inv + wdef * tk.w);
    ((float4*)out)[(size_t)t * (E_DIM / 4) + tid] = o4;
}

// ===========================================================================
// Launch
// ===========================================================================
extern "C" void kernel_launch(void* const* d_in, const int* in_sizes, int n_in,
                              void* d_out, int out_size)
{
    const float* tokens = (const float*)d_in[0];   // [T, E]
    const float* vocab  = (const float*)d_in[1];   // [V, E]
    const float* weight = (const float*)d_in[2];   // [E, E]
    const float* dEmb   = (const float*)d_in[3];   // [E]
    float* out = (float*)d_out;

    float *X, *Ld;
    __nv_bfloat16 *Xh, *Vh;
    cudaGetSymbolAddress((void**)&X,  g_X);
    cudaGetSymbolAddress((void**)&Ld, g_Ld);
    cudaGetSymbolAddress((void**)&Xh, g_Xh);
    cudaGetSymbolAddress((void**)&Vh, g_Vh);

    // 0) reset candidate counters / row maxima / identity flag (replay-safe)
    init_kernel<<<(T_DIM + 255) / 256, 256>>>();

    // 0b) device-side W==identity check
    check_ident_kernel<<<(E_DIM * E_DIM / 4) / 256, 256>>>(weight);

    // 1) vocab -> bf16 hi  (4 float4 per thread)
    {
        int n4 = V_DIM * E_DIM / 4;
        split_hi_kernel<<<(n4 + 1023) / 1024, 256>>>(vocab, Vh, n4);
    }

    // 2) X-prep: Xh (and X if W != I)
    xprep_kernel<<<dim3(E_DIM / BN, T_DIM / BM), 256>>>(tokens, weight, X, Xh);

    // 3) Ld = Xsrc @ default_embedding  (exact fp32)
    dot_default_kernel<<<T_DIM / 8, 256>>>(tokens, X, dEmb, Ld);

    // 4) fused bf16 GEMM + pruned candidate extraction
    cudaFuncSetAttribute(mma_gemm_cand_kernel,
                         cudaFuncAttributeMaxDynamicSharedMemorySize, GEMM_SMEM);
    mma_gemm_cand_kernel<<<dim3(T_DIM / 128, (V_DIM + 127) / 128), 256, GEMM_SMEM>>>(
        Xh, Vh);

    // 5) chunked filter + exact softmax + gather
    finalize_kernel<<<T_DIM, 256>>>(Ld, tokens, vocab, X, out);
}

// round 17
// speedup vs baseline: 1.0784x; 1.0784x over previous
#include <cuda_runtime.h>
#include <cuda_bf16.h>
#include <math.h>
#include <stdint.h>

// Problem dims (fixed by the reference)
#define T_DIM 8192
#define E_DIM 1024
#define V_DIM 50000

#define CAP     4096          // pre-candidate slots per row
#define WIN     22.0f         // pruning window (>= 20.72 + 1.0 + bf16 slack)
#define NWLOG   20.72f        // -ln(1e-9)
#define MARGIN  1.0f

// Scratch (allocation-free rule: __device__ globals)
__device__ float g_X[(size_t)T_DIM * E_DIM];                  // only if W != I
__device__ __nv_bfloat16 g_Xh[(size_t)T_DIM * E_DIM];         // 16 MB
__device__ __nv_bfloat16 g_Vh[(size_t)V_DIM * E_DIM];         // 100 MB
__device__ int2     g_cand[(size_t)T_DIM * CAP];              // 268 MB
__device__ int      g_cnt[T_DIM];
__device__ unsigned g_Mg[T_DIM];
__device__ int      g_Wident;                                 // W == identity?

// ===========================================================================
// helpers
// ===========================================================================
__device__ __forceinline__ uint32_t smem_u32(const void* p) {
    uint32_t a;
    asm("{ .reg .u64 t; cvta.to.shared.u64 t, %1; cvt.u32.u64 %0, t; }"
        : "=r"(a) : "l"(p));
    return a;
}

__device__ __forceinline__ void cp16(uint32_t dst, const void* src, uint32_t sz) {
    asm volatile("cp.async.cg.shared.global [%0], [%1], 16, %2;"
                 :: "r"(dst), "l"(src), "r"(sz) : "memory");
}

__device__ __forceinline__ void ldsm_x4(uint32_t& r0, uint32_t& r1,
                                        uint32_t& r2, uint32_t& r3, uint32_t addr) {
    asm volatile("ldmatrix.sync.aligned.m8n8.x4.shared.b16 {%0,%1,%2,%3}, [%4];"
                 : "=r"(r0), "=r"(r1), "=r"(r2), "=r"(r3) : "r"(addr));
}

__device__ __forceinline__ void mma_bf16(float* c, const uint32_t* a,
                                         uint32_t b0, uint32_t b1) {
    asm volatile(
        "mma.sync.aligned.m16n8k16.row.col.f32.bf16.bf16.f32 "
        "{%0,%1,%2,%3}, {%4,%5,%6,%7}, {%8,%9}, {%0,%1,%2,%3};"
        : "+f"(c[0]), "+f"(c[1]), "+f"(c[2]), "+f"(c[3])
        : "r"(a[0]), "r"(a[1]), "r"(a[2]), "r"(a[3]), "r"(b0), "r"(b1));
}

__device__ __forceinline__ uint32_t swz(uint32_t o) { return o ^ ((o >> 3) & 0x70); }

// order-preserving float <-> uint for atomicMax
__device__ __forceinline__ unsigned fenc(float f) {
    unsigned u = __float_as_uint(f);
    return (u & 0x80000000u) ? ~u : (u | 0x80000000u);
}
__device__ __forceinline__ float fdec(unsigned u) {
    unsigned i = (u & 0x80000000u) ? (u & 0x7FFFFFFFu) : ~u;
    return __uint_as_float(i);
}

// ===========================================================================
// init: reset counters / maxima / identity flag (every launch -> replay safe)
// ===========================================================================
__global__ void __launch_bounds__(256) init_kernel() {
    int i = blockIdx.x * 256 + threadIdx.x;
    if (i < T_DIM) { g_cnt[i] = 0; g_Mg[i] = fenc(-3.0e38f); }
    if (i == 0) g_Wident = 1;
}

// ===========================================================================
// check whether W is exactly the identity matrix (device-side, graph-safe)
// ===========================================================================
__global__ void __launch_bounds__(256) check_ident_kernel(
    const float* __restrict__ W)
{
    int i = blockIdx.x * 256 + threadIdx.x;     // float4 index
    float4 v = ((const float4*)W)[i];
    int base = 4 * i;
    int row  = base >> 10;                       // /E_DIM
    int col  = base & (E_DIM - 1);
    float e0 = (row == col + 0) ? 1.f : 0.f;
    float e1 = (row == col + 1) ? 1.f : 0.f;
    float e2 = (row == col + 2) ? 1.f : 0.f;
    float e3 = (row == col + 3) ? 1.f : 0.f;
    if (v.x != e0 || v.y != e1 || v.z != e2 || v.w != e3) g_Wident = 0;
}

// ===========================================================================
// fp32 -> bf16 (hi only), float4-vectorized, coalesced (R15-verified)
// ===========================================================================
__global__ void __launch_bounds__(256) split_hi_kernel(
    const float* __restrict__ src, __nv_bfloat16* __restrict__ dst, int n4)
{
    int i = blockIdx.x * 256 + threadIdx.x;
    if (i >= n4) return;
    float4 v = ((const float4*)src)[i];
    __nv_bfloat162* d = (__nv_bfloat162*)dst;
    d[2 * i]     = __nv_bfloat162(__float2bfloat16(v.x), __float2bfloat16(v.y));
    d[2 * i + 1] = __nv_bfloat162(__float2bfloat16(v.z), __float2bfloat16(v.w));
}

// ===========================================================================
// X-prep: identity -> Xh = bf16(tokens) directly (no X materialized);
// else exact fp32 GEMM X = tokens @ W, epilogue emits X (fp32) AND Xh (bf16)
// ===========================================================================
#define BM 128
#define BN 128
#define BK 16
#define TM 8
#define TN 8
#define SPAD 4

__global__ void __launch_bounds__(256) xprep_kernel(
    const float* __restrict__ A, const float* __restrict__ B,
    float* __restrict__ X, __nv_bfloat16* __restrict__ Xh)
{
    const int tid = threadIdx.x;
    const int bm = blockIdx.y * BM;
    const int bn = blockIdx.x * BN;

    if (g_Wident) {   // Xh tile = bf16(tokens tile); X not needed
        const float4* A4 = (const float4*)A;
        __nv_bfloat162* H2 = (__nv_bfloat162*)Xh;
#pragma unroll
        for (int r = 0; r < 16; ++r) {        // 128 rows x 32 float4 / 256 thr
            int f = tid + r * 256;
            int row = f >> 5, c4 = f & 31;
            float4 v = A4[(size_t)(bm + row) * (E_DIM / 4) + (bn >> 2) + c4];
            size_t h = (size_t)(bm + row) * (E_DIM / 2) + (bn >> 1) + c4 * 2;
            H2[h]     = __nv_bfloat162(__float2bfloat16(v.x), __float2bfloat16(v.y));
            H2[h + 1] = __nv_bfloat162(__float2bfloat16(v.z), __float2bfloat16(v.w));
        }
        return;
    }

    __shared__ float As[BK][BM + SPAD];
    __shared__ float Bs[BK][BN + SPAD];
    const int tx = tid & 15;
    const int ty = tid >> 4;

    float acc[TM][TN];
#pragma unroll
    for (int i = 0; i < TM; i++)
#pragma unroll
        for (int j = 0; j < TN; j++) acc[i][j] = 0.f;

    for (int k0 = 0; k0 < E_DIM; k0 += BK) {
#pragma unroll
        for (int r = 0; r < 2; r++) {
            int f = tid + r * 256;
            int row = f >> 2;
            int kq = (f & 3) * 4;
            float4 v = *(const float4*)&A[(size_t)(bm + row) * E_DIM + k0 + kq];
            As[kq + 0][row] = v.x; As[kq + 1][row] = v.y;
            As[kq + 2][row] = v.z; As[kq + 3][row] = v.w;
        }
#pragma unroll
        for (int r = 0; r < 2; r++) {
            int f = tid + r * 256;
            int kr = f >> 5;
            int nq = (f & 31) * 4;
            float4 v = *(const float4*)&B[(size_t)(k0 + kr) * E_DIM + bn + nq];
            Bs[kr][nq + 0] = v.x; Bs[kr][nq + 1] = v.y;
            Bs[kr][nq + 2] = v.z; Bs[kr][nq + 3] = v.w;
        }
        __syncthreads();
#pragma unroll
        for (int kk = 0; kk < BK; kk++) {
            float a[TM], b[TN];
#pragma unroll
            for (int i = 0; i < TM; i++) a[i] = As[kk][ty * TM + i];
#pragma unroll
            for (int j = 0; j < TN; j++) b[j] = Bs[kk][tx * TN + j];
#pragma unroll
            for (int i = 0; i < TM; i++)
#pragma unroll
                for (int j = 0; j < TN; j++) acc[i][j] += a[i] * b[j];
        }
        __syncthreads();
    }
#pragma unroll
    for (int i = 0; i < TM; i++) {
        int gm = bm + ty * TM + i;
#pragma unroll
        for (int j = 0; j < TN; j++)
            X[(size_t)gm * E_DIM + bn + tx * TN + j] = acc[i][j];
#pragma unroll
        for (int j = 0; j < TN; j += 2) {
            size_t h = ((size_t)gm * E_DIM + bn + tx * TN + j) >> 1;
            ((__nv_bfloat162*)Xh)[h] =
                __nv_bfloat162(__float2bfloat16(acc[i][j]),
                               __float2bfloat16(acc[i][j + 1]));
        }
    }
}

// ===========================================================================
// bf16 mma.sync GEMM + fused candidate extraction (R15-verified schedule:
// wait -> barrier -> mma -> tail prefetch; loads fly across the barrier).
// 128x128 CTA tile, 256 threads, 2 CTAs/SM, 3-stage cp.async pipeline.
// ===========================================================================
#define GBK 64
#define KITERS (E_DIM / GBK)              // 16
#define STAGE_B 32768                     // A 16K + B 16K per stage
#define GEMM_SMEM (3 * STAGE_B)           // 96 KB -> 2 CTAs/SM

__global__ void __launch_bounds__(256, 2) mma_gemm_cand_kernel(
    const __nv_bfloat16* __restrict__ A, const __nv_bfloat16* __restrict__ B)
{
    extern __shared__ __align__(1024) char sm[];
    const uint32_t sbase = smem_u32(sm);
    const int tid  = threadIdx.x;
    const int lane = tid & 31;
    const int wid  = tid >> 5;
    const int bm = blockIdx.x * 128;
    const int bn = blockIdx.y * 128;
    const int wm = (wid >> 2) * 64;
    const int wn = (wid & 3) * 32;

    float acc[4][4][4];
#pragma unroll
    for (int mt = 0; mt < 4; mt++)
#pragma unroll
        for (int nt = 0; nt < 4; nt++)
#pragma unroll
            for (int r = 0; r < 4; r++) acc[mt][nt][r] = 0.f;

    auto load_stage = [&](int s, int k0) {
        uint32_t sa = sbase + s * STAGE_B;
#pragma unroll
        for (int r = 0; r < 4; ++r) {               // A: 128 rows x 128B
            int f = tid + r * 256;
            int row = f >> 3, q = f & 7;
            uint32_t so = swz((uint32_t)(row * 128 + q * 16));
            cp16(sa + so,
                 (const char*)(A + (size_t)(bm + row) * E_DIM + k0) + q * 16, 16u);
        }
#pragma unroll
        for (int r = 0; r < 4; ++r) {               // B: 128 rows x 128B (guard V)
            int f = tid + r * 256;
            int row = f >> 3, q = f & 7;
            int vr = bn + row;
            uint32_t so = swz((uint32_t)(row * 128 + q * 16));
            const char* src = (const char*)(
                B + (size_t)(vr < V_DIM ? vr : V_DIM - 1) * E_DIM + k0) + q * 16;
            cp16(sa + 16384 + so, src, vr < V_DIM ? 16u : 0u);
        }
    };

    load_stage(0, 0);
    asm volatile("cp.async.commit_group;" ::: "memory");
    load_stage(1, GBK);
    asm volatile("cp.async.commit_group;" ::: "memory");

    for (int it = 0; it < KITERS; ++it) {
        // need group #it complete; allow 1 pending except the last iter
        if (it < KITERS - 1)
            asm volatile("cp.async.wait_group 1;" ::: "memory");
        else
            asm volatile("cp.async.wait_group 0;" ::: "memory");
        __syncthreads();

        uint32_t sa = sbase + (it % 3) * STAGE_B;
        uint32_t sb = sa + 16384;
#pragma unroll
        for (int ks = 0; ks < 4; ++ks) {
            uint32_t a[4][4], b[2][4];
#pragma unroll
            for (int mt = 0; mt < 4; ++mt) {
                int row  = wm + mt * 16 + (lane & 15);
                int colb = ks * 32 + ((lane >> 4) << 4);
                ldsm_x4(a[mt][0], a[mt][1], a[mt][2], a[mt][3],
                        sa + swz((uint32_t)(row * 128 + colb)));
            }
#pragma unroll
            for (int np = 0; np < 2; ++np) {
                int nrow = wn + np * 16 + ((lane >> 4) << 3) + (lane & 7);
                int colb = ks * 32 + (((lane >> 3) & 1) << 4);
                ldsm_x4(b[np][0], b[np][1], b[np][2], b[np][3],
                        sb + swz((uint32_t)(nrow * 128 + colb)));
            }
#pragma unroll
            for (int mt = 0; mt < 4; ++mt)
#pragma unroll
                for (int nt = 0; nt < 4; ++nt)
                    mma_bf16(acc[mt][nt], a[mt],
                             b[nt >> 1][(nt & 1) * 2], b[nt >> 1][(nt & 1) * 2 + 1]);
        }

        // tail prefetch: buffer (it+2)%3 was read in iter it-1 (all warps done)
        if (it + 2 < KITERS) {
            load_stage((it + 2) % 3, (it + 2) * GBK);
            asm volatile("cp.async.commit_group;" ::: "memory");
        }
    }
    __syncthreads();   // stage smem reused below

    // -------- fused epilogue: tile max -> atomicMax -> pruned append --------
    float* sm_m  = (float*)sm;            // [4][128]
    float* sm_mp = (float*)sm + 512;      // [128] combined(tile, running-global)

#pragma unroll
    for (int mt = 0; mt < 4; ++mt) {
        float v0 = -3.0e38f, v1 = -3.0e38f;
#pragma unroll
        for (int nt = 0; nt < 4; ++nt) {
            v0 = fmaxf(v0, fmaxf(acc[mt][nt][0], acc[mt][nt][1]));
            v1 = fmaxf(v1, fmaxf(acc[mt][nt][2], acc[mt][nt][3]));
        }
#pragma unroll
        for (int o = 1; o <= 2; o <<= 1) {
            v0 = fmaxf(v0, __shfl_xor_sync(0xffffffffu, v0, o));
            v1 = fmaxf(v1, __shfl_xor_sync(0xffffffffu, v1, o));
        }
        if ((lane & 3) == 0) {
            int r = wm + mt * 16 + (lane >> 2);
            sm_m[(wid & 3) * 128 + r]     = v0;
            sm_m[(wid & 3) * 128 + r + 8] = v1;
        }
    }
    __syncthreads();

    if (tid < 128) {
        float mp = fmaxf(fmaxf(sm_m[tid], sm_m[128 + tid]),
                         fmaxf(sm_m[256 + tid], sm_m[384 + tid]));
        unsigned old = atomicMax(&g_Mg[bm + tid], fenc(mp));
        sm_mp[tid] = fmaxf(mp, fdec(old));
    }
    __syncthreads();

#pragma unroll
    for (int mt = 0; mt < 4; ++mt) {
#pragma unroll
        for (int k = 0; k < 4; ++k) {
            int rloc = wm + mt * 16 + (lane >> 2) + ((k >> 1) << 3);
            float thr = sm_mp[rloc] - WIN;
#pragma unroll
            for (int nt = 0; nt < 4; ++nt) {
                float v = acc[mt][nt][k];
                if (v > thr) {
                    int col = bn + wn + nt * 8 + ((lane & 3) << 1) + (k & 1);
                    if (col < V_DIM) {
                        int gr = bm + rloc;
                        int slot = atomicAdd(&g_cnt[gr], 1);
                        if (slot < CAP)
                            g_cand[(size_t)gr * CAP + slot] =
                                make_int2(col, __float_as_int(v));
                    }
                }
            }
        }
    }
}

// ===========================================================================
// Final: filter -> CHUNKED exact dot + weighted gather (L1-hot window).
// Softmax uses fixed reference Mg (cancels exactly). Default-key logit ld
// is computed inline (dot kernel fused away).
// ===========================================================================
#define CAND_MAX 256
#define FCHUNK   8

__global__ void __launch_bounds__(256) finalize_kernel(
    const float* __restrict__ dEmb, const float* __restrict__ tokens,
    const float* __restrict__ vocab, const float* __restrict__ X,
    float* __restrict__ out)
{
    const int t = blockIdx.x;
    const int tid = threadIdx.x;
    const int lane = tid & 31;
    const int wid = tid >> 5;

    __shared__ int   s_idx[CAND_MAX];
    __shared__ float s_part[FCHUNK][8];
    __shared__ float s_w[FCHUNK];
    __shared__ int   s_cnt;
    __shared__ float s_zu;
    __shared__ float s_ld;
    __shared__ __align__(16) float sX[E_DIM];

    const float* xsrc = g_Wident ? tokens : X;
    ((float4*)sX)[tid] = ((const float4*)(xsrc + (size_t)t * E_DIM))[tid];
    if (tid == 0) { s_cnt = 0; s_zu = 0.f; }
    __syncthreads();

    const float4 x = ((const float4*)sX)[wid * 32 + lane];

    // ---- inline default-key logit: ld = dot(X[t], dEmb) (exact fp32) ----
    {
        float4 dv = ((const float4*)dEmb)[wid * 32 + lane];
        float s = x.x * dv.x + x.y * dv.y + x.z * dv.z + x.w * dv.w;
#pragma unroll
        for (int o = 16; o; o >>= 1) s += __shfl_xor_sync(0xffffffffu, s, o);
        if (lane == 0) s_part[0][wid] = s;
    }
    __syncthreads();
    if (tid == 0) {
        float d = 0.f;
#pragma unroll
        for (int w = 0; w < 8; ++w) d += s_part[0][w];
        s_ld = d;
    }
    __syncthreads();
    const float ld = s_ld;

    const float Mg = fdec(g_Mg[t]);
    const float cutoff = Mg - NWLOG - MARGIN;

    // filter pre-candidates
    const int pcnt = min(g_cnt[t], CAP);
    const int2* cl = &g_cand[(size_t)t * CAP];
    for (int i = tid; i < pcnt; i += 256) {
        int2 e = cl[i];
        if (__int_as_float(e.y) > cutoff) {
            int p = atomicAdd(&s_cnt, 1);
            if (p < CAND_MAX) s_idx[p] = e.x;
        }
    }
    __syncthreads();
    const int cnt = min(s_cnt, CAND_MAX);

    float4 acc = make_float4(0.f, 0.f, 0.f, 0.f);

    for (int c0 = 0; c0 < cnt; c0 += FCHUNK) {
        const int m = min(FCHUNK, cnt - c0);

        // exact fp32 dots for this chunk (warp-split, deterministic)
        for (int j = 0; j < m; ++j) {
            const float4* vr = (const float4*)(vocab + (size_t)s_idx[c0 + j] * E_DIM);
            float4 v = vr[wid * 32 + lane];
            float s = x.x * v.x + x.y * v.y + x.z * v.z + x.w * v.w;
#pragma unroll
            for (int o = 16; o; o >>= 1) s += __shfl_xor_sync(0xffffffffu, s, o);
            if (lane == 0) s_part[j][wid] = s;
        }
        __syncthreads();

        if (tid < m) {
            float d = 0.f;
#pragma unroll
            for (int w = 0; w < 8; ++w) d += s_part[tid][w];
            s_w[tid] = __expf(d - Mg);        // unnormalized weight
        }
        __syncthreads();

        if (tid == 0) {
            float z = 0.f;
            for (int j = 0; j < m; ++j) z += s_w[j];
            s_zu += z;
        }
        // weighted gather — rows are L1-hot from the dot pass just above
        for (int j = 0; j < m; ++j) {
            float w = s_w[j];
            float4 v = ((const float4*)(vocab + (size_t)s_idx[c0 + j] * E_DIM))[tid];
            acc.x += w * v.x; acc.y += w * v.y;
            acc.z += w * v.z; acc.w += w * v.w;
        }
        __syncthreads();   // protect s_part/s_w reuse and s_zu ordering
    }

    const float wdef_u = __expf(ld - Mg);
    const float inv = 1.0f / (s_zu + wdef_u);
    const float wdef = wdef_u * inv;

    float4 tk = ((const float4*)(tokens + (size_t)t * E_DIM))[tid];
    float4 o4 = make_float4(acc.x * inv + wdef * tk.x,
                            acc.y * inv + wdef * tk.y,
                            acc.z * inv + wdef * tk.z,
                            acc.w * inv + wdef * tk.w);
    ((float4*)out)[(size_t)t * (E_DIM / 4) + tid] = o4;
}

// ===========================================================================
// Launch
// ===========================================================================
extern "C" void kernel_launch(void* const* d_in, const int* in_sizes, int n_in,
                              void* d_out, int out_size)
{
    const float* tokens = (const float*)d_in[0];   // [T, E]
    const float* vocab  = (const float*)d_in[1];   // [V, E]
    const float* weight = (const float*)d_in[2];   // [E, E]
    const float* dEmb   = (const float*)d_in[3];   // [E]
    float* out = (float*)d_out;

    float *X;
    __nv_bfloat16 *Xh, *Vh;
    cudaGetSymbolAddress((void**)&X,  g_X);
    cudaGetSymbolAddress((void**)&Xh, g_Xh);
    cudaGetSymbolAddress((void**)&Vh, g_Vh);

    // 0) reset candidate counters / row maxima / identity flag (replay-safe)
    init_kernel<<<(T_DIM + 255) / 256, 256>>>();

    // 0b) device-side W==identity check
    check_ident_kernel<<<(E_DIM * E_DIM / 4) / 256, 256>>>(weight);

    // 1) vocab -> bf16 hi (coalesced)
    {
        int n4 = V_DIM * E_DIM / 4;
        split_hi_kernel<<<(n4 + 255) / 256, 256>>>(vocab, Vh, n4);
    }

    // 2) X-prep: Xh (and X if W != I)
    xprep_kernel<<<dim3(E_DIM / BN, T_DIM / BM), 256>>>(tokens, weight, X, Xh);

    // 3) fused bf16 GEMM + pruned candidate extraction
    cudaFuncSetAttribute(mma_gemm_cand_kernel,
                         cudaFuncAttributeMaxDynamicSharedMemorySize, GEMM_SMEM);
    mma_gemm_cand_kernel<<<dim3(T_DIM / 128, (V_DIM + 127) / 128), 256, GEMM_SMEM>>>(
        Xh, Vh);

    // 4) chunked filter + exact softmax + gather (default-key dot fused in)
    finalize_kernel<<<T_DIM, 256>>>(dEmb, tokens, vocab, X, out);
}